// round 7
// baseline (speedup 1.0000x reference)
#include <cuda_runtime.h>
#include <cuda_bf16.h>

#define BN 8
#define MO 12
#define DD 512
#define NO 37
#define NA 6
#define NT 3
#define EM 128
#define NAA 100
#define NC 300
#define KK 72
#define PP 5112            // KK*(KK-1)
#define FD 1536
#define HF 768
#define TPB 256
#define NDOT (NO+NA+6)     // 49 dots per head block

// grid layout: producers first, then dedicated pair blocks
#define HEADB (BN*MO)              // 96
#define PPB   8                    // pool parts per batch
#define POOLB (BN*PPB)             // 64
#define TABB  8
#define PRODT (HEADB + POOLB + TABB)       // 168
#define PBPB  21                           // pair blocks per batch
#define PAIRB (BN*PBPB)                    // 168
#define GRID  (PRODT + PAIRB)              // 336

// output layout (flattened, tuple order)
#define OFF_FINAL 0
#define OFF_PL    (BN*NC)
#define OFF_TT    (OFF_PL + BN*PP*NT)
#define OFF_ACT   (OFF_TT + BN*PP*NT)
#define OFF_OBJ   (OFF_ACT + BN*MO*NA)

// ---------------- device scratch ----------------
__device__ int      g_sel6[BN*MO];
__device__ int      g_aaidx[BN*KK];
__device__ int      g_objidx[BN*MO];
__device__ float    g_inpdot[BN*MO*6];
__device__ float    g_objtab[NO*6];
__device__ float    g_acttab[NA*6];
__device__ float    g_nonexist[BN*NC];
__device__ unsigned g_segmax[BN*NC];
__device__ float    g_invconst[NT];
__device__ int      g_headdone[BN];  // 12 each
__device__ int      g_pooldone[BN];  // 8 each
__device__ int      g_pairdone[BN];  // 21 each
__device__ int      g_tabdone;       // 8
__device__ int      g_ctrE;          // everyone done -> reset

__device__ __forceinline__ float warpsum(float v){
    #pragma unroll
    for(int o=16;o>0;o>>=1) v += __shfl_xor_sync(0xffffffffu, v, o);
    return v;
}
__device__ __forceinline__ unsigned fmap(float f){
    unsigned u=__float_as_uint(f);
    return (u & 0x80000000u) ? ~u : (u | 0x80000000u);
}
__device__ __forceinline__ float funmap(unsigned u){
    return __uint_as_float((u & 0x80000000u) ? (u ^ 0x80000000u) : ~u);
}
__device__ __forceinline__ float dot4(float4 a, float4 b){
    return a.x*b.x + a.y*b.y + a.z*b.z + a.w*b.w;
}
__device__ __forceinline__ int ldvol(int* p){ return *((volatile int*)p); }

__device__ __forceinline__ const float4* head_wptr(int c, const float* W_obj,
                                                   const float* W_act, const float* W_tr){
    if(c<NO)    return (const float4*)(W_obj + (size_t)c*DD);
    if(c<NO+NA) return (const float4*)(W_act + (size_t)(c-NO)*DD);
    int idx=c-NO-NA, t=idx>>1, h=idx&1;
    return (const float4*)(W_tr + (size_t)t*FD + h*HF);
}

__global__ __launch_bounds__(TPB, 3) void
kFused(const float* __restrict__ inp, const float* __restrict__ objmask,
       const float* __restrict__ W_obj, const float* __restrict__ b_obj,
       const float* __restrict__ W_act, const float* __restrict__ b_act,
       const float* __restrict__ W_tr,  const float* __restrict__ b_tr,
       const float* __restrict__ W_ne,  const float* __restrict__ b_ne,
       const float* __restrict__ obj_emb, const float* __restrict__ act_emb,
       const int* __restrict__ AA, const float* __restrict__ TR,
       const int* __restrict__ lookup, float* __restrict__ out){
    int blk = blockIdx.x;
    int tid = threadIdx.x, w = tid>>5, lane = tid&31;

    if(blk < HEADB){
        // ======== head block (b,o): 49 dot-512, split-K (one 64-chunk per unit) ========
        __shared__ float4 row4[DD/4];
        __shared__ float  part[NDOT*8];
        __shared__ float  res[NO+NA];
        int bo = blk, b = bo/MO, o = bo%MO;
        const float4* ir = (const float4*)(inp + (size_t)bo*DD);
        if(tid < DD/4) row4[tid] = ir[tid];
        __syncthreads();
        {   // unit 0: u = tid  (u < 392 always)
            int u = tid, c = u>>3, ch = u&7;
            const float4* W = head_wptr(c, W_obj, W_act, W_tr) + ch*16;
            const float4* R = row4 + ch*16;
            float s = 0.f;
            #pragma unroll
            for(int l=0;l<16;l++) s += dot4(R[l], W[l]);
            part[u] = s;
        }
        if(tid < NDOT*8 - 256){  // unit 1: u = tid+256
            int u = tid+256, c = u>>3, ch = u&7;
            const float4* W = head_wptr(c, W_obj, W_act, W_tr) + ch*16;
            const float4* R = row4 + ch*16;
            float s = 0.f;
            #pragma unroll
            for(int l=0;l<16;l++) s += dot4(R[l], W[l]);
            part[u] = s;
        }
        __syncthreads();
        if(tid < NDOT){
            float v = 0.f;
            #pragma unroll
            for(int l=0;l<8;l++) v += part[tid*8+l];
            int c = tid;
            if(c<NO){ float x=v+b_obj[c]; res[c]=x; out[OFF_OBJ + bo*NO + c]=x; }
            else if(c<NO+NA){ float x=v+b_act[c-NO]; res[c]=x; out[OFF_ACT + bo*NA + (c-NO)]=x; }
            else __stcg(&g_inpdot[bo*6 + (c-NO-NA)], v);
        }
        __syncthreads();
        if(w==0){
            // warp-parallel argmax, first-index tie-break
            float bv = -3.4e38f; int bi = 0;
            for(int c=lane; c<NO; c+=32){ float v=res[c]; if(v>bv){ bv=v; bi=c; } }
            #pragma unroll
            for(int o2=16;o2>0;o2>>=1){
                float ov = __shfl_xor_sync(0xffffffffu, bv, o2);
                int   oi = __shfl_xor_sync(0xffffffffu, bi, o2);
                if(ov>bv || (ov==bv && oi<bi)){ bv=ov; bi=oi; }
            }
            if(lane==0) __stcg(&g_objidx[bo], bi);
            bool s=false;
            if(lane < NA){
                int k = o*NA + lane;
                bool act_on = (res[NO+lane] > 0.0f) && (objmask[bo] == 1.0f);
                int  aa = AA[b*KK + k];
                s = act_on && (aa != -1);
                __stcg(&g_aaidx[b*KK+k], s ? aa : -1);
            }
            unsigned m = __ballot_sync(0xffffffffu, s);
            if(lane==0) __stcg(&g_sel6[bo], (int)(m & 0x3fu));
        }
        __threadfence();
        __syncthreads();
        if(tid==0) atomicAdd(&g_headdone[b], 1);
    } else if(blk < HEADB + POOLB){
        // ======== pool block (b,part): 38 dot-512 of W_ne vs pooled mean ========
        __shared__ float4 pooled4[DD/4];
        __shared__ float  part[38*8];
        int bb = blk - HEADB;
        int b = bb/PPB, pt = bb%PPB;
        if(tid < DD/4){
            float msum = 0.f;
            float4 s = make_float4(0,0,0,0);
            #pragma unroll
            for(int o=0;o<MO;o++){
                float m = objmask[b*MO+o];
                float4 v = ((const float4*)(inp + ((size_t)b*MO+o)*DD))[tid];
                msum += m;
                s.x += v.x*m; s.y += v.y*m; s.z += v.z*m; s.w += v.w*m;
            }
            float inv = 1.0f/msum;
            pooled4[tid] = make_float4(s.x*inv, s.y*inv, s.z*inv, s.w*inv);
        }
        __syncthreads();
        int c0 = pt*38;
        {   int u = tid, cl = u>>3, ch = u&7, c = c0+cl;
            float s = 0.f;
            if(c < NC){
                const float4* W = (const float4*)(W_ne + (size_t)c*DD) + ch*16;
                const float4* R = pooled4 + ch*16;
                #pragma unroll
                for(int l=0;l<16;l++) s += dot4(R[l], W[l]);
            }
            part[u] = s;
        }
        if(tid < 38*8 - 256){
            int u = tid+256, cl = u>>3, ch = u&7, c = c0+cl;
            float s = 0.f;
            if(c < NC){
                const float4* W = (const float4*)(W_ne + (size_t)c*DD) + ch*16;
                const float4* R = pooled4 + ch*16;
                #pragma unroll
                for(int l=0;l<16;l++) s += dot4(R[l], W[l]);
            }
            part[u] = s;
        }
        __syncthreads();
        if(tid < 38 && c0+tid < NC){
            float v = 0.f;
            #pragma unroll
            for(int l=0;l<8;l++) v += part[tid*8+l];
            __stcg(&g_nonexist[b*NC + c0 + tid], v + b_ne[c0+tid]);
        }
        __threadfence();
        __syncthreads();
        if(tid==0) atomicAdd(&g_pooldone[b], 1);
    } else if(blk < PRODT){
        // ======== tab blocks: emb tables + invconst + clear segmax ========
        int tb = blk - HEADB - POOLB;
        int gw = tb*8 + w;      // 0..63
        for(int c=gw; c<NO*6 + NA*6 + NT; c+=64){
            if(c < NO*6 + NA*6){
                const float* src; const float* Wv;
                if(c < NO*6){
                    int oi=c/6, idx=c%6, t=idx>>1, h=idx&1;
                    src = obj_emb + (size_t)oi*EM;
                    Wv  = W_tr + (size_t)t*FD + h*HF + DD;
                } else {
                    int cc=c-NO*6; int a=cc/6, idx=cc%6, t=idx>>1, h=idx&1;
                    src = act_emb + (size_t)a*EM;
                    Wv  = W_tr + (size_t)t*FD + h*HF + DD + EM;
                }
                float4 a4 = ((const float4*)src)[lane];
                float4 b4 = ((const float4*)Wv)[lane];
                float acc = warpsum(dot4(a4,b4));
                if(lane==0){
                    if(c < NO*6) __stcg(&g_objtab[c], acc);
                    else         __stcg(&g_acttab[c-NO*6], acc);
                }
            } else {
                int t = c - NO*6 - NA*6;
                const float4* W = (const float4*)(W_tr + (size_t)t*FD);
                float acc=0.f;
                #pragma unroll
                for(int d=lane; d<FD/4; d+=32) acc += W[d].x+W[d].y+W[d].z+W[d].w;
                acc = warpsum(acc);
                if(lane==0) __stcg(&g_invconst[t], b_tr[t] - acc);
            }
        }
        for(int i=tb*300+tid; i<(tb+1)*300 && i<BN*NC; i+=TPB) __stcg(&g_segmax[i], 0u);
        __threadfence();
        __syncthreads();
        if(tid==0) atomicAdd(&g_tabdone, 1);
    } else {
        // ======== pair block: prefetch TR, wait for batch producers, emit ========
        __shared__ float s1s[KK*NT], s2s[KK*NT], invc[NT], btr[NT];
        __shared__ int   aas[KK], sel6s[MO];
        __shared__ short cps[KK+1];
        __shared__ unsigned char sels[KK];
        __shared__ int   sh_last;
        int pb = blk - PRODT;
        int b2 = pb/PBPB, sub = pb%PBPB;
        int p = sub*TPB + tid;
        bool inb = p < PP;
        int i=0, j=0;
        float tr0=0.f, tr1=0.f, tr2=0.f;
        if(inb){
            i = p/(KK-1); int r = p - i*(KK-1);
            j = (r<i) ? r : r+1;
            const float* trp = TR + (((size_t)b2*KK + i)*KK + j)*NT;
            tr0 = __ldg(trp); tr1 = __ldg(trp+1); tr2 = __ldg(trp+2);
        }
        if(tid < NT) btr[tid] = b_tr[tid];

        if(tid==0){
            while(ldvol(&g_headdone[b2]) < MO) { }
            while(ldvol(&g_tabdone) < TABB) { }
        }
        __syncthreads();
        __threadfence();

        if(tid < MO) sel6s[tid] = __ldcg(&g_sel6[b2*MO+tid]);
        if(tid < KK){
            int k=tid, o=k/NA, a=k%NA;
            int oi = __ldcg(&g_objidx[b2*MO+o]);
            aas[k] = __ldcg(&g_aaidx[b2*KK+k]);
            #pragma unroll
            for(int t=0;t<NT;t++){
                s1s[k*NT+t] = __ldcg(&g_inpdot[(b2*MO+o)*6 + t*2+0]) + __ldcg(&g_objtab[oi*6 + t*2+0]) + __ldcg(&g_acttab[a*6 + t*2+0]);
                s2s[k*NT+t] = __ldcg(&g_inpdot[(b2*MO+o)*6 + t*2+1]) + __ldcg(&g_objtab[oi*6 + t*2+1]) + __ldcg(&g_acttab[a*6 + t*2+1]);
            }
        }
        if(tid < NT) invc[tid] = __ldcg(&g_invconst[tid]);
        __syncthreads();
        if(tid <= KK){
            int full = tid/NA, rem = tid%NA, c = 0;
            for(int o=0;o<full;o++) c += __popc(sel6s[o]);
            if(tid < KK) c += __popc(sel6s[full] & ((1<<rem)-1));
            cps[tid] = (short)c;
            if(tid < KK) sels[tid] = (unsigned char)((sel6s[full]>>rem) & 1);
        }
        __syncthreads();

        if(inb){
            int S = cps[KK];
            int si = sels[i];
            int vb = cps[i]*(S-1) + si*(cps[j] - (i<j ? 1 : 0));
            bool valid = si && sels[j];
            int q = valid ? vb : S*(S-1) + (p - vb);
            float* pl = out + OFF_PL + ((size_t)b2*PP + q)*NT;
            float* tt = out + OFF_TT + ((size_t)b2*PP + q)*NT;
            if(valid){
                const int* lk = lookup + ((size_t)aas[i]*NAA + aas[j])*NT;
                float l0 = s1s[i*NT+0] + s2s[j*NT+0] + btr[0];
                float l1 = s1s[i*NT+1] + s2s[j*NT+1] + btr[1];
                float l2 = s1s[i*NT+2] + s2s[j*NT+2] + btr[2];
                pl[0]=l0; pl[1]=l1; pl[2]=l2;
                tt[0]=tr0; tt[1]=tr1; tt[2]=tr2;
                atomicMax(&g_segmax[b2*NC + lk[0]], fmap(l0));
                atomicMax(&g_segmax[b2*NC + lk[1]], fmap(l1));
                atomicMax(&g_segmax[b2*NC + lk[2]], fmap(l2));
            } else {
                pl[0]=invc[0]; pl[1]=invc[1]; pl[2]=invc[2];
                tt[0]=-1.0f; tt[1]=-1.0f; tt[2]=-1.0f;
            }
        }

        // per-batch finalize by the last pair block of this batch
        __threadfence();
        __syncthreads();
        if(tid==0){
            int old = atomicAdd(&g_pairdone[b2], 1);
            sh_last = (old == PBPB-1);
        }
        __syncthreads();
        if(sh_last){
            if(tid==0){ while(ldvol(&g_pooldone[b2]) < PPB) { } }
            __syncthreads();
            __threadfence();
            for(int c=tid; c<NC; c+=TPB){
                int idx = b2*NC + c;
                unsigned u = __ldcg(&g_segmax[idx]);
                out[OFF_FINAL + idx] = u ? funmap(u) : __ldcg(&g_nonexist[idx]);
            }
        }
    }

    // ---------------- global completion + counter reset for graph replay ----------------
    __syncthreads();
    if(tid==0){
        int old = atomicAdd(&g_ctrE, 1);
        if(old == GRID-1){
            // every block has passed all its spins
            #pragma unroll
            for(int b=0;b<BN;b++){
                *((volatile int*)&g_headdone[b]) = 0;
                *((volatile int*)&g_pooldone[b]) = 0;
                *((volatile int*)&g_pairdone[b]) = 0;
            }
            *((volatile int*)&g_tabdone) = 0;
            *((volatile int*)&g_ctrE) = 0;
        }
    }
}

extern "C" void kernel_launch(void* const* d_in, const int* in_sizes, int n_in,
                              void* d_out, int out_size){
    const float* inp     = (const float*)d_in[0];
    const float* objmask = (const float*)d_in[1];
    const float* TR      = (const float*)d_in[2];
    const float* W_obj   = (const float*)d_in[3];
    const float* b_obj   = (const float*)d_in[4];
    const float* W_act   = (const float*)d_in[5];
    const float* b_act   = (const float*)d_in[6];
    const float* W_tr    = (const float*)d_in[7];
    const float* b_tr    = (const float*)d_in[8];
    const float* W_ne    = (const float*)d_in[9];
    const float* b_ne    = (const float*)d_in[10];
    const float* obj_emb = (const float*)d_in[11];
    const float* act_emb = (const float*)d_in[12];
    const int*   AA      = (const int*)d_in[13];
    const int*   lookup  = (const int*)d_in[15];
    float* out = (float*)d_out;

    kFused<<<GRID, TPB>>>(inp, objmask, W_obj, b_obj, W_act, b_act,
                          W_tr, b_tr, W_ne, b_ne, obj_emb, act_emb,
                          AA, TR, lookup, out);
}

// round 8
// speedup vs baseline: 1.3172x; 1.3172x over previous
#include <cuda_runtime.h>
#include <cuda_bf16.h>

#define BN 8
#define MO 12
#define DD 512
#define NO 37
#define NA 6
#define NT 3
#define EM 128
#define NAA 100
#define NC 300
#define KK 72
#define PP 5112            // KK*(KK-1)
#define FD 1536
#define HF 768
#define NB 10              // kC blocks per batch
#define NCB (BN*NB)        // kC grid = 80
#define NTH (NB*256)       // threads per batch in kC

// kA grid layout (R3 proven)
#define HEADB (BN*MO)      // 96
#define PPB   8
#define POOLB (BN*PPB)     // 64
#define TABB  4
#define KA_GRID (HEADB + POOLB + TABB + 1)   // 165

// output layout (flattened, tuple order)
#define OFF_FINAL 0
#define OFF_PL    (BN*NC)
#define OFF_TT    (OFF_PL + BN*PP*NT)
#define OFF_ACT   (OFF_TT + BN*PP*NT)
#define OFF_OBJ   (OFF_ACT + BN*MO*NA)

// ---------------- device scratch ----------------
__device__ int      g_sel6[BN*MO];
__device__ int      g_aaidx[BN*KK];
__device__ int      g_objidx[BN*MO];
__device__ float    g_inpdot[BN*MO*6];
__device__ float    g_objtab[NO*6];
__device__ float    g_acttab[NA*6];
__device__ float    g_nonexist[BN*NC];
__device__ unsigned g_segmax[BN*NC];
__device__ float    g_invconst[NT];
__device__ int      g_ctr;

__device__ __forceinline__ float warpsum(float v){
    #pragma unroll
    for(int o=16;o>0;o>>=1) v += __shfl_xor_sync(0xffffffffu, v, o);
    return v;
}
__device__ __forceinline__ unsigned fmap(float f){
    unsigned u=__float_as_uint(f);
    return (u & 0x80000000u) ? ~u : (u | 0x80000000u);
}
__device__ __forceinline__ float funmap(unsigned u){
    return __uint_as_float((u & 0x80000000u) ? (u ^ 0x80000000u) : ~u);
}
__device__ __forceinline__ float dot4(float4 a, float4 b){
    return a.x*b.x + a.y*b.y + a.z*b.z + a.w*b.w;
}

// ================ kA: heads + pool + tables + clear (verbatim R3, proven) ================
__global__ __launch_bounds__(512) void
kA(const float* __restrict__ inp, const float* __restrict__ objmask,
   const float* __restrict__ W_obj, const float* __restrict__ b_obj,
   const float* __restrict__ W_act, const float* __restrict__ b_act,
   const float* __restrict__ W_tr,  const float* __restrict__ b_tr,
   const float* __restrict__ W_ne,  const float* __restrict__ b_ne,
   const float* __restrict__ obj_emb, const float* __restrict__ act_emb,
   const int* __restrict__ AA, float* __restrict__ out){
    int blk = blockIdx.x;
    int tid = threadIdx.x, w = tid>>5, lane = tid&31;

    if(blk < HEADB){
        __shared__ float4 row[DD/4];
        __shared__ float  res[NO+NA];
        int bo = blk, b = bo/MO, o = bo%MO;
        const float4* ir = (const float4*)(inp + (size_t)bo*DD);
        if(tid < DD/4) row[tid]=ir[tid];
        __syncthreads();
        for(int c=w; c<NO+NA+6; c+=16){
            const float4* W;
            if(c<NO)            W = (const float4*)(W_obj + (size_t)c*DD);
            else if(c<NO+NA)    W = (const float4*)(W_act + (size_t)(c-NO)*DD);
            else { int idx=c-NO-NA; int t=idx>>1, h=idx&1;
                   W = (const float4*)(W_tr + (size_t)t*FD + h*HF); }
            float acc=0.f;
            #pragma unroll
            for(int d=lane; d<DD/4; d+=32) acc += dot4(row[d], W[d]);
            acc = warpsum(acc);
            if(lane==0){
                if(c<NO){ float v=acc+b_obj[c]; res[c]=v; out[OFF_OBJ + bo*NO + c]=v; }
                else if(c<NO+NA){ float v=acc+b_act[c-NO]; res[c]=v; out[OFF_ACT + bo*NA + (c-NO)]=v; }
                else g_inpdot[bo*6 + (c-NO-NA)] = acc;
            }
        }
        __syncthreads();
        if(tid==0){
            int best=0; float bv=res[0];
            #pragma unroll
            for(int c=1;c<NO;c++) if(res[c]>bv){ bv=res[c]; best=c; }
            g_objidx[bo]=best;
        }
        if(w==0){
            bool s=false;
            if(lane < NA){
                int k = o*NA + lane;
                bool act_on = (res[NO+lane] > 0.0f) && (objmask[bo] == 1.0f);
                int  aa = AA[b*KK + k];
                s = act_on && (aa != -1);
                g_aaidx[b*KK+k] = s ? aa : -1;
            }
            unsigned m = __ballot_sync(0xffffffffu, s);
            if(lane==0) g_sel6[bo] = (int)(m & 0x3fu);
        }
    } else if(blk < HEADB + POOLB){
        int bb = blk - HEADB;
        int b = bb/PPB, part = bb%PPB;
        __shared__ float4 pooled[DD/4];
        __shared__ float  msum_s;
        if(tid==0){
            float m=0.f;
            for(int o=0;o<MO;o++) m += objmask[b*MO+o];
            msum_s=m;
        }
        __syncthreads();
        float inv = 1.0f/msum_s;
        if(tid < DD/4){
            float4 s = make_float4(0,0,0,0);
            #pragma unroll
            for(int o=0;o<MO;o++){
                float m = objmask[b*MO+o];
                float4 v = ((const float4*)(inp + ((size_t)b*MO+o)*DD))[tid];
                s.x += v.x*m; s.y += v.y*m; s.z += v.z*m; s.w += v.w*m;
            }
            pooled[tid] = make_float4(s.x*inv, s.y*inv, s.z*inv, s.w*inv);
        }
        __syncthreads();
        int c0 = part*38, c1 = c0+38; if(c1>NC) c1=NC;
        for(int c=c0+w; c<c1; c+=16){
            const float4* W = (const float4*)(W_ne + (size_t)c*DD);
            float acc=0.f;
            #pragma unroll
            for(int d=lane; d<DD/4; d+=32) acc += dot4(pooled[d], W[d]);
            acc = warpsum(acc);
            if(lane==0) g_nonexist[b*NC+c] = acc + b_ne[c];
        }
    } else if(blk < HEADB + POOLB + TABB){
        int gw = (blk - HEADB - POOLB)*16 + w;      // 0..63
        for(int c=gw; c<NO*6 + NA*6 + NT; c+=64){
            if(c < NO*6 + NA*6){
                const float* src; const float* Wv;
                if(c < NO*6){
                    int oi=c/6, idx=c%6, t=idx>>1, h=idx&1;
                    src = obj_emb + (size_t)oi*EM;
                    Wv  = W_tr + (size_t)t*FD + h*HF + DD;
                } else {
                    int cc=c-NO*6; int a=cc/6, idx=cc%6, t=idx>>1, h=idx&1;
                    src = act_emb + (size_t)a*EM;
                    Wv  = W_tr + (size_t)t*FD + h*HF + DD + EM;
                }
                float4 a4 = ((const float4*)src)[lane];
                float4 b4 = ((const float4*)Wv)[lane];
                float acc = warpsum(dot4(a4,b4));
                if(lane==0){
                    if(c < NO*6) g_objtab[c] = acc;
                    else         g_acttab[c-NO*6] = acc;
                }
            } else {
                int t = c - NO*6 - NA*6;
                const float4* W = (const float4*)(W_tr + (size_t)t*FD);
                float acc=0.f;
                #pragma unroll
                for(int d=lane; d<FD/4; d+=32) acc += W[d].x+W[d].y+W[d].z+W[d].w;
                acc = warpsum(acc);
                if(lane==0) g_invconst[t] = b_tr[t] - acc;
            }
        }
    } else {
        for(int i=tid; i<BN*NC; i+=512) g_segmax[i]=0u;
        if(tid==0) g_ctr=0;
    }
}

// ================ kC: valid prefix (coalesced) + vectorized invalid tail + finalize ================
__global__ __launch_bounds__(256) void
kC(const float* __restrict__ TR, const float* __restrict__ b_tr,
   const int* __restrict__ lookup, float* __restrict__ out){
    int b = blockIdx.x / NB, sub = blockIdx.x % NB;
    int tid = threadIdx.x;
    __shared__ float s1s[KK*NT], s2s[KK*NT], invc[NT], btr[NT];
    __shared__ int   aas[KK], sel6s[MO];
    __shared__ short cps[KK+1];
    __shared__ unsigned char listS[KK];
    __shared__ int   lastF;

    if(tid < MO) sel6s[tid] = g_sel6[b*MO+tid];
    if(tid < KK){
        int k=tid, o=k/NA, a=k%NA;
        int oi = g_objidx[b*MO+o];
        aas[k] = g_aaidx[b*KK+k];
        #pragma unroll
        for(int t=0;t<NT;t++){
            s1s[k*NT+t] = g_inpdot[(b*MO+o)*6 + t*2+0] + g_objtab[oi*6 + t*2+0] + g_acttab[a*6 + t*2+0];
            s2s[k*NT+t] = g_inpdot[(b*MO+o)*6 + t*2+1] + g_objtab[oi*6 + t*2+1] + g_acttab[a*6 + t*2+1];
        }
    }
    if(tid < NT){ invc[tid]=g_invconst[tid]; btr[tid]=b_tr[tid]; }
    __syncthreads();
    if(tid <= KK){
        int full = tid/NA, rem = tid%NA, c = 0;
        for(int o=0;o<full;o++) c += __popc(sel6s[o]);
        if(tid < KK) c += __popc(sel6s[full] & ((1<<rem)-1));
        cps[tid] = (short)c;
    }
    __syncthreads();
    if(tid < KK){
        if((sel6s[tid/NA]>>(tid%NA)) & 1) listS[cps[tid]] = (unsigned char)tid;
    }
    __syncthreads();

    int S = cps[KK];
    int SS1 = S*(S-1);
    float* plb = out + OFF_PL + (size_t)b*PP*NT;
    float* ttb = out + OFF_TT + (size_t)b*PP*NT;
    int lt = sub*256 + tid;

    // ---- valid prefix: coalesced writes at q, list-based inverse map ----
    for(int q = lt; q < SS1; q += NTH){
        int a = q/(S-1), r = q - a*(S-1);
        int i = listS[a];
        int j = listS[r<a ? r : r+1];
        float l0 = s1s[i*NT+0] + s2s[j*NT+0] + btr[0];
        float l1 = s1s[i*NT+1] + s2s[j*NT+1] + btr[1];
        float l2 = s1s[i*NT+2] + s2s[j*NT+2] + btr[2];
        plb[q*3+0]=l0; plb[q*3+1]=l1; plb[q*3+2]=l2;
        const float* trp = TR + (((size_t)b*KK + i)*KK + j)*NT;
        ttb[q*3+0]=trp[0]; ttb[q*3+1]=trp[1]; ttb[q*3+2]=trp[2];
        const int* lk = lookup + ((size_t)aas[i]*NAA + aas[j])*NT;
        atomicMax(&g_segmax[b*NC + lk[0]], fmap(l0));
        atomicMax(&g_segmax[b*NC + lk[1]], fmap(l1));
        atomicMax(&g_segmax[b*NC + lk[2]], fmap(l2));
    }

    // ---- invalid tail: periodic constant fill with float4 ----
    {
        int F0 = SS1*3;                  // first tail float index (per-batch)
        const int FE = PP*3;             // 15336
        int start4 = (F0+3) & ~3;
        if(sub==0 && tid < start4-F0){
            plb[F0+tid] = invc[(F0+tid)%3];
            ttb[F0+tid] = -1.0f;
        }
        float4 pat[3];
        #pragma unroll
        for(int m=0;m<3;m++)
            pat[m] = make_float4(invc[(4*m+0)%3], invc[(4*m+1)%3],
                                 invc[(4*m+2)%3], invc[(4*m+3)%3]);
        const float4 neg1 = make_float4(-1.f,-1.f,-1.f,-1.f);
        float4* pl4 = (float4*)plb;
        float4* tt4 = (float4*)ttb;
        for(int v = start4/4 + lt; v < FE/4; v += NTH){
            pl4[v] = pat[v%3];
            tt4[v] = neg1;
        }
    }

    // ---- last-block finalize ----
    __threadfence();
    __syncthreads();
    if(tid==0){
        int old = atomicAdd(&g_ctr, 1);
        lastF = (old == NCB-1);
    }
    __syncthreads();
    if(lastF){
        __threadfence();
        for(int idx=tid; idx<BN*NC; idx+=256){
            unsigned u = __ldcg(&g_segmax[idx]);
            out[OFF_FINAL + idx] = u ? funmap(u) : g_nonexist[idx];
        }
    }
}

extern "C" void kernel_launch(void* const* d_in, const int* in_sizes, int n_in,
                              void* d_out, int out_size){
    const float* inp     = (const float*)d_in[0];
    const float* objmask = (const float*)d_in[1];
    const float* TR      = (const float*)d_in[2];
    const float* W_obj   = (const float*)d_in[3];
    const float* b_obj   = (const float*)d_in[4];
    const float* W_act   = (const float*)d_in[5];
    const float* b_act   = (const float*)d_in[6];
    const float* W_tr    = (const float*)d_in[7];
    const float* b_tr    = (const float*)d_in[8];
    const float* W_ne    = (const float*)d_in[9];
    const float* b_ne    = (const float*)d_in[10];
    const float* obj_emb = (const float*)d_in[11];
    const float* act_emb = (const float*)d_in[12];
    const int*   AA      = (const int*)d_in[13];
    const int*   lookup  = (const int*)d_in[15];
    float* out = (float*)d_out;

    kA<<<KA_GRID, 512>>>(inp, objmask, W_obj, b_obj, W_act, b_act,
                         W_tr, b_tr, W_ne, b_ne, obj_emb, act_emb, AA, out);
    kC<<<NCB, 256>>>(TR, b_tr, lookup, out);
}

// round 9
// speedup vs baseline: 1.3371x; 1.0152x over previous
#include <cuda_runtime.h>
#include <cuda_bf16.h>

#define BN 8
#define MO 12
#define DD 512
#define NO 37
#define NA 6
#define NT 3
#define EM 128
#define NAA 100
#define NC 300
#define KK 72
#define PP 5112            // KK*(KK-1)
#define FD 1536
#define HF 768
#define IT 5               // items per thread in kC (1024*5 >= 5112)

// kA grid layout (R3 proven, minus clear block)
#define HEADB (BN*MO)      // 96
#define PPB   8
#define POOLB (BN*PPB)     // 64
#define TABB  4
#define KA_GRID (HEADB + POOLB + TABB)   // 164

// output layout (flattened, tuple order)
#define OFF_FINAL 0
#define OFF_PL    (BN*NC)
#define OFF_TT    (OFF_PL + BN*PP*NT)
#define OFF_ACT   (OFF_TT + BN*PP*NT)
#define OFF_OBJ   (OFF_ACT + BN*MO*NA)

// ---------------- device scratch ----------------
__device__ int      g_sel6[BN*MO];
__device__ int      g_aaidx[BN*KK];
__device__ int      g_objidx[BN*MO];
__device__ float    g_inpdot[BN*MO*6];
__device__ float    g_objtab[NO*6];
__device__ float    g_acttab[NA*6];
__device__ float    g_nonexist[BN*NC];
__device__ float    g_invconst[NT];

__device__ __forceinline__ float warpsum(float v){
    #pragma unroll
    for(int o=16;o>0;o>>=1) v += __shfl_xor_sync(0xffffffffu, v, o);
    return v;
}
__device__ __forceinline__ unsigned fmap(float f){
    unsigned u=__float_as_uint(f);
    return (u & 0x80000000u) ? ~u : (u | 0x80000000u);
}
__device__ __forceinline__ float funmap(unsigned u){
    return __uint_as_float((u & 0x80000000u) ? (u ^ 0x80000000u) : ~u);
}
__device__ __forceinline__ float dot4(float4 a, float4 b){
    return a.x*b.x + a.y*b.y + a.z*b.z + a.w*b.w;
}

// ================ kA: heads + pool + tables (verbatim R3, proven) ================
__global__ __launch_bounds__(512) void
kA(const float* __restrict__ inp, const float* __restrict__ objmask,
   const float* __restrict__ W_obj, const float* __restrict__ b_obj,
   const float* __restrict__ W_act, const float* __restrict__ b_act,
   const float* __restrict__ W_tr,  const float* __restrict__ b_tr,
   const float* __restrict__ W_ne,  const float* __restrict__ b_ne,
   const float* __restrict__ obj_emb, const float* __restrict__ act_emb,
   const int* __restrict__ AA, float* __restrict__ out){
    int blk = blockIdx.x;
    int tid = threadIdx.x, w = tid>>5, lane = tid&31;

    if(blk < HEADB){
        __shared__ float4 row[DD/4];
        __shared__ float  res[NO+NA];
        int bo = blk, b = bo/MO, o = bo%MO;
        const float4* ir = (const float4*)(inp + (size_t)bo*DD);
        if(tid < DD/4) row[tid]=ir[tid];
        __syncthreads();
        for(int c=w; c<NO+NA+6; c+=16){
            const float4* W;
            if(c<NO)            W = (const float4*)(W_obj + (size_t)c*DD);
            else if(c<NO+NA)    W = (const float4*)(W_act + (size_t)(c-NO)*DD);
            else { int idx=c-NO-NA; int t=idx>>1, h=idx&1;
                   W = (const float4*)(W_tr + (size_t)t*FD + h*HF); }
            float acc=0.f;
            #pragma unroll
            for(int d=lane; d<DD/4; d+=32) acc += dot4(row[d], W[d]);
            acc = warpsum(acc);
            if(lane==0){
                if(c<NO){ float v=acc+b_obj[c]; res[c]=v; out[OFF_OBJ + bo*NO + c]=v; }
                else if(c<NO+NA){ float v=acc+b_act[c-NO]; res[c]=v; out[OFF_ACT + bo*NA + (c-NO)]=v; }
                else g_inpdot[bo*6 + (c-NO-NA)] = acc;
            }
        }
        __syncthreads();
        if(tid==0){
            int best=0; float bv=res[0];
            #pragma unroll
            for(int c=1;c<NO;c++) if(res[c]>bv){ bv=res[c]; best=c; }
            g_objidx[bo]=best;
        }
        if(w==0){
            bool s=false;
            if(lane < NA){
                int k = o*NA + lane;
                bool act_on = (res[NO+lane] > 0.0f) && (objmask[bo] == 1.0f);
                int  aa = AA[b*KK + k];
                s = act_on && (aa != -1);
                g_aaidx[b*KK+k] = s ? aa : -1;
            }
            unsigned m = __ballot_sync(0xffffffffu, s);
            if(lane==0) g_sel6[bo] = (int)(m & 0x3fu);
        }
    } else if(blk < HEADB + POOLB){
        int bb = blk - HEADB;
        int b = bb/PPB, part = bb%PPB;
        __shared__ float4 pooled[DD/4];
        __shared__ float  msum_s;
        if(tid==0){
            float m=0.f;
            for(int o=0;o<MO;o++) m += objmask[b*MO+o];
            msum_s=m;
        }
        __syncthreads();
        float inv = 1.0f/msum_s;
        if(tid < DD/4){
            float4 s = make_float4(0,0,0,0);
            #pragma unroll
            for(int o=0;o<MO;o++){
                float m = objmask[b*MO+o];
                float4 v = ((const float4*)(inp + ((size_t)b*MO+o)*DD))[tid];
                s.x += v.x*m; s.y += v.y*m; s.z += v.z*m; s.w += v.w*m;
            }
            pooled[tid] = make_float4(s.x*inv, s.y*inv, s.z*inv, s.w*inv);
        }
        __syncthreads();
        int c0 = part*38, c1 = c0+38; if(c1>NC) c1=NC;
        for(int c=c0+w; c<c1; c+=16){
            const float4* W = (const float4*)(W_ne + (size_t)c*DD);
            float acc=0.f;
            #pragma unroll
            for(int d=lane; d<DD/4; d+=32) acc += dot4(pooled[d], W[d]);
            acc = warpsum(acc);
            if(lane==0) g_nonexist[b*NC+c] = acc + b_ne[c];
        }
    } else {
        int gw = (blk - HEADB - POOLB)*16 + w;      // 0..63
        for(int c=gw; c<NO*6 + NA*6 + NT; c+=64){
            if(c < NO*6 + NA*6){
                const float* src; const float* Wv;
                if(c < NO*6){
                    int oi=c/6, idx=c%6, t=idx>>1, h=idx&1;
                    src = obj_emb + (size_t)oi*EM;
                    Wv  = W_tr + (size_t)t*FD + h*HF + DD;
                } else {
                    int cc=c-NO*6; int a=cc/6, idx=cc%6, t=idx>>1, h=idx&1;
                    src = act_emb + (size_t)a*EM;
                    Wv  = W_tr + (size_t)t*FD + h*HF + DD + EM;
                }
                float4 a4 = ((const float4*)src)[lane];
                float4 b4 = ((const float4*)Wv)[lane];
                float acc = warpsum(dot4(a4,b4));
                if(lane==0){
                    if(c < NO*6) g_objtab[c] = acc;
                    else         g_acttab[c-NO*6] = acc;
                }
            } else {
                int t = c - NO*6 - NA*6;
                const float4* W = (const float4*)(W_tr + (size_t)t*FD);
                float acc=0.f;
                #pragma unroll
                for(int d=lane; d<FD/4; d+=32) acc += W[d].x+W[d].y+W[d].z+W[d].w;
                acc = warpsum(acc);
                if(lane==0) g_invconst[t] = b_tr[t] - acc;
            }
        }
    }
}

// ================ kC: one block per batch; smem segmax; TR prefetched ================
__global__ __launch_bounds__(1024) void
kC(const float* __restrict__ TR, const float* __restrict__ b_tr,
   const int* __restrict__ lookup, float* __restrict__ out){
    int b = blockIdx.x;
    int tid = threadIdx.x;

    __shared__ float s1s[KK*NT], s2s[KK*NT], invc[NT], btr[NT];
    __shared__ int   aas[KK], sel6s[MO];
    __shared__ short cps[KK+1];
    __shared__ unsigned char sels[KK];
    __shared__ unsigned segS[NC];
    __shared__ float nexS[NC];

    // ---- TR prefetch: pure function of p, no prologue dependency ----
    float tr[IT][NT];
    #pragma unroll
    for(int it=0; it<IT; it++){
        int p = it*1024 + tid;
        if(p < PP){
            int i = p/(KK-1), r = p - i*(KK-1);
            int j = (r<i) ? r : r+1;
            const float* trp = TR + (((size_t)b*KK + i)*KK + j)*NT;
            tr[it][0]=__ldg(trp); tr[it][1]=__ldg(trp+1); tr[it][2]=__ldg(trp+2);
        }
    }

    // ---- prologue loads (overlap with TR trip) ----
    if(tid < MO) sel6s[tid] = g_sel6[b*MO+tid];
    if(tid < KK){
        int k=tid, o=k/NA, a=k%NA;
        int oi = g_objidx[b*MO+o];
        aas[k] = g_aaidx[b*KK+k];
        #pragma unroll
        for(int t=0;t<NT;t++){
            s1s[k*NT+t] = g_inpdot[(b*MO+o)*6 + t*2+0] + g_objtab[oi*6 + t*2+0] + g_acttab[a*6 + t*2+0];
            s2s[k*NT+t] = g_inpdot[(b*MO+o)*6 + t*2+1] + g_objtab[oi*6 + t*2+1] + g_acttab[a*6 + t*2+1];
        }
    }
    if(tid < NT){ invc[tid]=g_invconst[tid]; btr[tid]=b_tr[tid]; }
    if(tid < NC){ segS[tid]=0u; nexS[tid]=g_nonexist[b*NC+tid]; }
    __syncthreads();
    if(tid <= KK){
        int full = tid/NA, rem = tid%NA, c = 0;
        for(int o=0;o<full;o++) c += __popc(sel6s[o]);
        if(tid < KK) c += __popc(sel6s[full] & ((1<<rem)-1));
        cps[tid] = (short)c;
        if(tid < KK) sels[tid] = (unsigned char)((sel6s[full]>>rem) & 1);
    }
    __syncthreads();

    int S = cps[KK];
    float* plb = out + OFF_PL + (size_t)b*PP*NT;
    float* ttb = out + OFF_TT + (size_t)b*PP*NT;

    #pragma unroll
    for(int it=0; it<IT; it++){
        int p = it*1024 + tid;
        if(p < PP){
            int i = p/(KK-1), r = p - i*(KK-1);
            int j = (r<i) ? r : r+1;
            int si = sels[i];
            int vb = cps[i]*(S-1) + si*(cps[j] - (i<j ? 1 : 0));
            bool valid = si && sels[j];
            int q = valid ? vb : S*(S-1) + (p - vb);
            float* pl = plb + q*NT;
            float* tt = ttb + q*NT;
            if(valid){
                const int* lk = lookup + ((size_t)aas[i]*NAA + aas[j])*NT;
                float l0 = s1s[i*NT+0] + s2s[j*NT+0] + btr[0];
                float l1 = s1s[i*NT+1] + s2s[j*NT+1] + btr[1];
                float l2 = s1s[i*NT+2] + s2s[j*NT+2] + btr[2];
                pl[0]=l0; pl[1]=l1; pl[2]=l2;
                tt[0]=tr[it][0]; tt[1]=tr[it][1]; tt[2]=tr[it][2];
                atomicMax(&segS[lk[0]], fmap(l0));
                atomicMax(&segS[lk[1]], fmap(l1));
                atomicMax(&segS[lk[2]], fmap(l2));
            } else {
                pl[0]=invc[0]; pl[1]=invc[1]; pl[2]=invc[2];
                tt[0]=-1.0f; tt[1]=-1.0f; tt[2]=-1.0f;
            }
        }
    }

    // ---- finalize: smem segmax -> out, no global round-trip ----
    __syncthreads();
    if(tid < NC){
        unsigned u = segS[tid];
        out[OFF_FINAL + b*NC + tid] = u ? funmap(u) : nexS[tid];
    }
}

extern "C" void kernel_launch(void* const* d_in, const int* in_sizes, int n_in,
                              void* d_out, int out_size){
    const float* inp     = (const float*)d_in[0];
    const float* objmask = (const float*)d_in[1];
    const float* TR      = (const float*)d_in[2];
    const float* W_obj   = (const float*)d_in[3];
    const float* b_obj   = (const float*)d_in[4];
    const float* W_act   = (const float*)d_in[5];
    const float* b_act   = (const float*)d_in[6];
    const float* W_tr    = (const float*)d_in[7];
    const float* b_tr    = (const float*)d_in[8];
    const float* W_ne    = (const float*)d_in[9];
    const float* b_ne    = (const float*)d_in[10];
    const float* obj_emb = (const float*)d_in[11];
    const float* act_emb = (const float*)d_in[12];
    const int*   AA      = (const int*)d_in[13];
    const int*   lookup  = (const int*)d_in[15];
    float* out = (float*)d_out;

    kA<<<KA_GRID, 512>>>(inp, objmask, W_obj, b_obj, W_act, b_act,
                         W_tr, b_tr, W_ne, b_ne, obj_emb, act_emb, AA, out);
    kC<<<BN, 1024>>>(TR, b_tr, lookup, out);
}